// round 1
// baseline (speedup 1.0000x reference)
#include <cuda_runtime.h>
#include <math.h>

#define C 32
#define LAYERS 4
#define NFIX 2
#define MAXN 100000
#define MAXE 1600000

// Scratch (device globals — no runtime allocation allowed)
__device__ __align__(16) float g_dZ[(size_t)LAYERS * MAXN * C];
__device__ __align__(16) float g_agg[(size_t)LAYERS * MAXN * C];
__device__ __align__(16) float g_Z[(size_t)LAYERS * MAXN * C];

__device__ __forceinline__ float silu_f(float x) {
    return x * (1.0f / (1.0f + __expf(-x)));
}

// ---------------------------------------------------------------------------
// Kernel 1: per (node, layer):  h = silu([Z_l, f] @ Kf_l);  dZ = h @ K_l
// Also zeroes agg for this iteration. Weights staged in SMEM (broadcast LDS).
// grid: (ceil(N/256), L), block 256. One thread per node.
// ---------------------------------------------------------------------------
__global__ void node_forward_kernel(const float* __restrict__ Z,
                                    const float* __restrict__ f,
                                    const float* __restrict__ Kf,
                                    const float* __restrict__ K,
                                    float* __restrict__ dZ,
                                    float* __restrict__ agg,
                                    int N, int useZ)
{
    __shared__ float Kfs[2 * C * C];   // 8 KB
    __shared__ float Ks[C * C];        // 4 KB
    const int l = blockIdx.y;
    const float* Kfl = Kf + (size_t)l * 2 * C * C;
    const float* Kl  = K  + (size_t)l * C * C;
    for (int i = threadIdx.x; i < 2 * C * C; i += blockDim.x) Kfs[i] = Kfl[i];
    for (int i = threadIdx.x; i < C * C;     i += blockDim.x) Ks[i]  = Kl[i];
    __syncthreads();

    const int n = blockIdx.x * blockDim.x + threadIdx.x;
    if (n >= N) return;

    float h[C];
#pragma unroll
    for (int c = 0; c < C; c++) h[c] = 0.f;

    if (useZ) {
        const float4* zr = (const float4*)(Z + ((size_t)l * N + n) * C);
#pragma unroll
        for (int k4 = 0; k4 < C / 4; k4++) {
            float4 zv = zr[k4];
            float zs[4] = {zv.x, zv.y, zv.z, zv.w};
#pragma unroll
            for (int kk = 0; kk < 4; kk++) {
                const float* kr = &Kfs[(k4 * 4 + kk) * C];
#pragma unroll
                for (int c = 0; c < C; c++) h[c] = fmaf(zs[kk], kr[c], h[c]);
            }
        }
    }
    {
        const float4* fr = (const float4*)(f + (size_t)n * C);
#pragma unroll
        for (int k4 = 0; k4 < C / 4; k4++) {
            float4 fv = fr[k4];
            float fs[4] = {fv.x, fv.y, fv.z, fv.w};
#pragma unroll
            for (int kk = 0; kk < 4; kk++) {
                const float* kr = &Kfs[(C + k4 * 4 + kk) * C];
#pragma unroll
                for (int c = 0; c < C; c++) h[c] = fmaf(fs[kk], kr[c], h[c]);
            }
        }
    }
#pragma unroll
    for (int c = 0; c < C; c++) h[c] = silu_f(h[c]);

    float d[C];
#pragma unroll
    for (int c = 0; c < C; c++) d[c] = 0.f;
#pragma unroll
    for (int k = 0; k < C; k++) {
        const float* kr = &Ks[k * C];
#pragma unroll
        for (int c = 0; c < C; c++) d[c] = fmaf(h[k], kr[c], d[c]);
    }

    float4* dzr  = (float4*)(dZ  + ((size_t)l * N + n) * C);
    float4* aggr = (float4*)(agg + ((size_t)l * N + n) * C);
    const float4 z4 = make_float4(0.f, 0.f, 0.f, 0.f);
#pragma unroll
    for (int c4 = 0; c4 < C / 4; c4++) {
        dzr[c4]  = make_float4(d[c4 * 4], d[c4 * 4 + 1], d[c4 * 4 + 2], d[c4 * 4 + 3]);
        aggr[c4] = z4;
    }
}

// ---------------------------------------------------------------------------
// Kernel 2: edges. 8 threads per edge (4 channels each), all 4 layers in-loop.
//   g = silu(w * (dZ[s] - dZ[t]));  red.add.v4 -> agg[s]
// dZ/agg are L2-resident (51MB each), so gathers hit L2.
// ---------------------------------------------------------------------------
__global__ void edge_kernel(const int* __restrict__ ei,
                            const float* __restrict__ ew,
                            const float* __restrict__ dZ,
                            float* __restrict__ agg,
                            int N, int E)
{
    const int idx = blockIdx.x * blockDim.x + threadIdx.x;
    const int e   = idx >> 3;
    const int sub = idx & 7;
    if (e >= E) return;

    const int s = __ldg(ei + e);
    const int t = __ldg(ei + E + e);
    const float w = __ldg(ew + e);

#pragma unroll
    for (int l = 0; l < LAYERS; l++) {
        const float4* ps = (const float4*)(dZ + ((size_t)l * N + s) * C) + sub;
        const float4* pt = (const float4*)(dZ + ((size_t)l * N + t) * C) + sub;
        float4 a = __ldg(ps);
        float4 b = __ldg(pt);
        float gx = silu_f(w * (a.x - b.x));
        float gy = silu_f(w * (a.y - b.y));
        float gz = silu_f(w * (a.z - b.z));
        float gw = silu_f(w * (a.w - b.w));
        float* dst = agg + ((size_t)l * N + s) * C + sub * 4;
        asm volatile("red.global.add.v4.f32 [%0], {%1, %2, %3, %4};"
                     :: "l"(dst), "f"(gx), "f"(gy), "f"(gz), "f"(gw)
                     : "memory");
    }
}

// ---------------------------------------------------------------------------
// Kernel 3: warp per node.  Y_l = -(agg_l @ K_l^T) (+X for l=3), then tridiag
// across layers (per-channel scalar recurrences), write Z (and optional Z[-1]).
// K is pre-transposed into SMEM so lane reads are conflict-free.
// ---------------------------------------------------------------------------
__global__ void tridiag_kernel(const float* __restrict__ agg,
                               const float* __restrict__ K,
                               const float* __restrict__ X,
                               float* __restrict__ Zout,
                               float* __restrict__ lastOut,
                               int N)
{
    __shared__ float KT[LAYERS][C][C];  // KT[l][j][c] = K[l][c][j], 16 KB
    for (int i = threadIdx.x; i < LAYERS * C * C; i += blockDim.x) {
        int l = i >> 10;
        int c = (i >> 5) & 31;
        int j = i & 31;
        KT[l][j][c] = K[i];
    }
    __syncthreads();

    const int gw   = (blockIdx.x * blockDim.x + threadIdx.x) >> 5;
    const int lane = threadIdx.x & 31;
    if (gw >= N) return;

    float Y[LAYERS];
#pragma unroll
    for (int l = 0; l < LAYERS; l++) {
        float av  = agg[((size_t)l * N + gw) * C + lane];
        float acc = 0.f;
#pragma unroll
        for (int j = 0; j < C; j++)
            acc = fmaf(__shfl_sync(0xffffffffu, av, j), KT[l][j][lane], acc);
        Y[l] = -acc;
    }
    Y[3] += X[(size_t)gw * C + lane];

    // forward substitution: Y'_0 = sqrt(1/2) Y0 ; Y'_i = a_i (b_i Y'_{i-1} + Y_i)
    const float s12 = 0.70710678118654752f;  // sqrt(1/2)
    const float s23 = 0.81649658092772603f;  // sqrt(2/3)
    const float s34 = 0.86602540378443865f;  // sqrt(3/4)
    const float s45 = 0.89442719099991588f;  // sqrt(4/5)
    float t0 = s12 * Y[0];
    float t1 = s23 * (s12 * t0 + Y[1]);
    float t2 = s34 * (s23 * t1 + Y[2]);
    float t3 = s45 * (s34 * t2 + Y[3]);
    // backward substitution
    float w3 = s45 * t3;
    float w2 = s34 * (s34 * w3 + t2);
    float w1 = s23 * (s23 * w2 + t1);
    float w0 = s12 * (s12 * w1 + t0);

    const size_t base = (size_t)gw * C + lane;
    const size_t NC   = (size_t)N * C;
    Zout[0 * NC + base] = w0;
    Zout[1 * NC + base] = w1;
    Zout[2 * NC + base] = w2;
    Zout[3 * NC + base] = w3;
    if (lastOut) lastOut[base] = w3;
}

// ---------------------------------------------------------------------------
extern "C" void kernel_launch(void* const* d_in, const int* in_sizes, int n_in,
                              void* d_out, int out_size)
{
    const float* X  = (const float*)d_in[0];
    const float* f  = (const float*)d_in[1];
    const int*   ei = (const int*)d_in[2];
    const float* ew = (const float*)d_in[3];
    const float* K  = (const float*)d_in[4];
    const float* Kf = (const float*)d_in[5];

    const int N = in_sizes[0] / C;
    const int E = in_sizes[3];

    float *dZ, *agg, *Zb;
    cudaGetSymbolAddress((void**)&dZ,  g_dZ);
    cudaGetSymbolAddress((void**)&agg, g_agg);
    cudaGetSymbolAddress((void**)&Zb,  g_Z);

    const size_t NC = (size_t)N * C;
    float* out = (float*)d_out;
    float* Zfinal;
    float* lastPtr;
    if ((size_t)out_size >= (size_t)(LAYERS + 1) * NC) {
        lastPtr = out;            // Z[-1] first
        Zfinal  = out + NC;       // then full Z
    } else if ((size_t)out_size >= (size_t)LAYERS * NC) {
        Zfinal  = out;
        lastPtr = nullptr;
    } else {
        Zfinal  = Zb;
        lastPtr = out;
    }

    dim3 nodeGrid((N + 255) / 256, LAYERS);
    const int edgeBlocks = (E * 8 + 255) / 256;
    const int triBlocks  = (N * 32 + 255) / 256;

    for (int it = 0; it < NFIX; it++) {
        node_forward_kernel<<<nodeGrid, 256>>>(Zb, f, Kf, K, dZ, agg, N, it > 0 ? 1 : 0);
        edge_kernel<<<edgeBlocks, 256>>>(ei, ew, dZ, agg, N, E);
        const bool last = (it == NFIX - 1);
        tridiag_kernel<<<triBlocks, 256>>>(agg, K, X,
                                           last ? Zfinal : Zb,
                                           last ? lastPtr : nullptr,
                                           N);
    }
}